// round 15
// baseline (speedup 1.0000x reference)
#include <cuda_runtime.h>
#include <cuda_fp16.h>

#define HID 5
#define HDIM 2048
#define BSZ 16384

__device__ int g_lengths[BSZ];

// ---------------------------------------------------------------------------
// Kernel 1: per-row nonzero count (ragged length, matches reference mask)
// ---------------------------------------------------------------------------
__global__ void len_kernel(const float* __restrict__ x) {
    int b = blockIdx.x;
    const float4* row = reinterpret_cast<const float4*>(x + (size_t)b * HDIM);
    int tid = threadIdx.x;
    int cnt = 0;
#pragma unroll
    for (int i = 0; i < 2; i++) {
        float4 v = row[tid + i * 256];
        cnt += (v.x != 0.f) + (v.y != 0.f) + (v.z != 0.f) + (v.w != 0.f);
    }
    __shared__ int s[8];
#pragma unroll
    for (int o = 16; o > 0; o >>= 1) cnt += __shfl_down_sync(0xffffffffu, cnt, o);
    if ((tid & 31) == 0) s[tid >> 5] = cnt;
    __syncthreads();
    if (tid < 8) {
        int v = s[tid];
#pragma unroll
        for (int o = 4; o > 0; o >>= 1) v += __shfl_down_sync(0xffu, v, o);
        if (tid == 0) g_lengths[b] = v;
    }
}

// ---------------------------------------------------------------------------
// math helpers
// ---------------------------------------------------------------------------
__device__ __forceinline__ float fast_tanh(float v) {
    float r; asm("tanh.approx.f32 %0, %1;" : "=f"(r) : "f"(v)); return r;
}
__device__ __forceinline__ __half2 tanh2(__half2 v) {
    unsigned u = *reinterpret_cast<unsigned*>(&v), r;
    asm("tanh.approx.f16x2 %0, %1;" : "=r"(r) : "r"(u));
    return *reinterpret_cast<__half2*>(&r);
}

// ---------------------------------------------------------------------------
// LSTM, software-pipelined with EXPLICIT STAGGER (in-order warp issue model):
// acc(t) is ready at step start (double buffer). Source order interleaves
//   tanh2 of unit u+1  ->  chain of unit u  ->  GEMV columns of unit u
// so every MUFU rt-8 gap and chain stall has ready fma work behind it.
// Pairs P_u={0.5i,0.5f}, Q_u={0.5o, g}; sigmoids+tanh(g) f16x2;
// cn / tanh(cn) / h fp32. Accumulation order (x, h0..h4) == R10.
// ---------------------------------------------------------------------------
struct State {
    float c[HID];
    float h[HID];
};

template<bool GUARDED>
__device__ __forceinline__ void lstm_step(State& st,
    __half2* accP, __half2* accQ, float xnext, bool upd,
    const __half2* __restrict__ wihP, const __half2* __restrict__ wihQ,
    const __half2* __restrict__ bsP,  const __half2* __restrict__ bsQ,
    const __half2 (*whhP)[HID], const __half2 (*whhQ)[HID])
{
    const __half2 h05 = __float2half2_rn(0.5f);
    const __half2 xn = __float2half2_rn(xnext);

    __half2 nxtP[HID], nxtQ[HID];
    __half2 tP[HID], tQ[HID];

    // prologue of the pipeline: first two tanh pairs + x-seed of next gates
    tP[0] = tanh2(accP[0]); tQ[0] = tanh2(accQ[0]);
    tP[1] = tanh2(accP[1]); tQ[1] = tanh2(accQ[1]);
#pragma unroll
    for (int p = 0; p < HID; p++) {
        nxtP[p] = __hfma2(xn, wihP[p], bsP[p]);
        nxtQ[p] = __hfma2(xn, wihQ[p], bsQ[p]);
    }

#pragma unroll
    for (int u = 0; u < HID; u++) {
        // keep 2 tanh pairs in flight ahead of the consuming chain
        if (u + 2 < HID) {
            tP[u + 2] = tanh2(accP[u + 2]);
            tQ[u + 2] = tanh2(accQ[u + 2]);
        }
        // chain of unit u (consumes tP/tQ[u], issued >=2 MUFU slots ago)
        const __half2 sP = __hfma2(tP[u], h05, h05);     // {ig, fg}
        const float ig = __low2float(sP);
        const float fg = __high2float(sP);
        const float og = fmaf(__low2float(tQ[u]), 0.5f, 0.5f);
        const float tg = __high2float(tQ[u]);
        const float cn = fmaf(fg, st.c[u], ig * tg);
        const float hn = og * fast_tanh(cn);
        float hc;
        if (GUARDED) {
            hc = upd ? hn : st.h[u];
            if (upd) { st.c[u] = cn; st.h[u] = hn; }
        } else {
            st.c[u] = cn; st.h[u] = hn; hc = hn;
        }
        const __half2 hb = __float2half2_rn(hc);
        // GEMV column u of next step's gates (independent fma work that
        // fills the latency shadow of units u+1.. tanh/chains)
#pragma unroll
        for (int p = 0; p < HID; p++) {
            nxtP[p] = __hfma2(hb, whhP[p][u], nxtP[p]);
            nxtQ[p] = __hfma2(hb, whhQ[p][u], nxtQ[p]);
        }
    }
#pragma unroll
    for (int p = 0; p < HID; p++) { accP[p] = nxtP[p]; accQ[p] = nxtQ[p]; }
}

__global__ void __launch_bounds__(64, 1) lstm_kernel(
    const float* __restrict__ x,
    const float* __restrict__ W_ih,
    const float* __restrict__ W_hh,
    const float* __restrict__ b_ih,
    const float* __restrict__ b_hh,
    float* __restrict__ out)
{
    int b = blockIdx.x * blockDim.x + threadIdx.x;

    // gate rows: i:0-4  f:5-9  g:10-14  o:15-19
    __half2 wihP[HID], wihQ[HID], bsP[HID], bsQ[HID];
    __half2 whhP[HID][HID], whhQ[HID][HID];   // [pair][column j]
#pragma unroll
    for (int u = 0; u < HID; u++) {
        const int ri = u, rf = HID + u, rg = 2 * HID + u, ro = 3 * HID + u;
        wihP[u] = __floats2half2_rn(0.5f * W_ih[ri], 0.5f * W_ih[rf]);
        wihQ[u] = __floats2half2_rn(0.5f * W_ih[ro], W_ih[rg]);
        bsP[u]  = __floats2half2_rn(0.5f * (b_ih[ri] + b_hh[ri]),
                                    0.5f * (b_ih[rf] + b_hh[rf]));
        bsQ[u]  = __floats2half2_rn(0.5f * (b_ih[ro] + b_hh[ro]),
                                    (b_ih[rg] + b_hh[rg]));
#pragma unroll
        for (int j = 0; j < HID; j++) {
            whhP[u][j] = __floats2half2_rn(0.5f * W_hh[ri * HID + j],
                                           0.5f * W_hh[rf * HID + j]);
            whhQ[u][j] = __floats2half2_rn(0.5f * W_hh[ro * HID + j],
                                           W_hh[rg * HID + j]);
        }
    }

    const int len = g_lengths[b];
    const float* row = x + (size_t)b * HDIM;

    State st;
#pragma unroll
    for (int u = 0; u < HID; u++) { st.c[u] = 0.f; st.h[u] = 0.f; }

    float4 a0 = make_float4(0.f, 0.f, 0.f, 0.f);
    if (len > 0) a0 = *reinterpret_cast<const float4*>(row);

    // prologue: gates for t=0 (h=0 -> bias + x0*wih)
    __half2 accP[HID], accQ[HID];
    {
        const __half2 x0 = __float2half2_rn(a0.x);
#pragma unroll
        for (int p = 0; p < HID; p++) {
            accP[p] = __hfma2(x0, wihP[p], bsP[p]);
            accQ[p] = __hfma2(x0, wihQ[p], bsQ[p]);
        }
    }

    for (int t0 = 0; t0 < len; t0 += 4) {
        // prefetch next 4 timesteps (HDIM multiple of 4)
        float4 nx = a0;
        const int nt = t0 + 4;
        if (nt < HDIM) nx = *reinterpret_cast<const float4*>(row + nt);

        const int nrem = len - t0;
        if (nrem >= 4) {
            lstm_step<false>(st, accP, accQ, a0.y, true, wihP, wihQ, bsP, bsQ, whhP, whhQ);
            lstm_step<false>(st, accP, accQ, a0.z, true, wihP, wihQ, bsP, bsQ, whhP, whhQ);
            lstm_step<false>(st, accP, accQ, a0.w, true, wihP, wihQ, bsP, bsQ, whhP, whhQ);
            lstm_step<false>(st, accP, accQ, nx.x, true, wihP, wihQ, bsP, bsQ, whhP, whhQ);
        } else {
            const float xn[4] = {a0.y, a0.z, a0.w, nx.x};
#pragma unroll
            for (int k = 0; k < 4; k++)
                lstm_step<true>(st, accP, accQ, xn[k], k < nrem,
                                wihP, wihQ, bsP, bsQ, whhP, whhQ);
        }
        a0 = nx;
    }

#pragma unroll
    for (int u = 0; u < HID; u++) out[b * HID + u] = st.h[u];
}

// ---------------------------------------------------------------------------
extern "C" void kernel_launch(void* const* d_in, const int* in_sizes, int n_in,
                              void* d_out, int out_size) {
    const float* x    = (const float*)d_in[0];
    const float* W_ih = (const float*)d_in[1];
    const float* W_hh = (const float*)d_in[2];
    const float* b_ih = (const float*)d_in[3];
    const float* b_hh = (const float*)d_in[4];
    float* out = (float*)d_out;

    len_kernel<<<BSZ, 256>>>(x);
    lstm_kernel<<<BSZ / 64, 64>>>(x, W_ih, W_hh, b_ih, b_hh, out);
}